// round 3
// baseline (speedup 1.0000x reference)
#include <cuda_runtime.h>
#include <math.h>

// ---------------- problem constants ----------------
#define B   4
#define N0  8192   // finest
#define N1  2048
#define N2  512    // coarsest
#define D0  128    // x0 channels
#define D1C 256    // x1 channels
#define D2C 512    // x2 channels
#define DI  768    // intermediate channels (D1C + D2C)
#define DT  896    // output channels (D0 + DI)

// ---------------- scratch (device globals; no allocation allowed) ----------------
__device__ float4 g_s4[B * N1];            // coarse-point prep, max S = 2048
__device__ float  g_x2t[B * N2 * D2C];     // x2 transposed to [B, S, D]
__device__ float  g_inter[B * N1 * DI];    // stage-1 result, point-major [B, N1, 768]
__device__ int    g_idx[B * N0 * 3];
__device__ float  g_w[B * N0 * 3];

// ---------------- prep: coarse points -> (-2x,-2y,-2z,|p|^2) ----------------
__global__ void prep_kernel(const float* __restrict__ xyz, int total) {
    int i = blockIdx.x * blockDim.x + threadIdx.x;
    if (i < total) {
        float x = xyz[3 * i], y = xyz[3 * i + 1], z = xyz[3 * i + 2];
        g_s4[i] = make_float4(-2.f * x, -2.f * y, -2.f * z, x * x + y * y + z * z);
    }
}

// ---------------- transpose [B, R, C] -> [B, C, R] (R=C=512 here) ----------------
__global__ void transpose_kernel(const float* __restrict__ src, float* __restrict__ dst,
                                 int R, int C) {
    __shared__ float tile[32][33];
    int b  = blockIdx.z;
    int c0 = blockIdx.x * 32, r0 = blockIdx.y * 32;
    const float* s = src + (size_t)b * R * C;
    float*       d = dst + (size_t)b * R * C;
    int c = c0 + threadIdx.x;
    #pragma unroll
    for (int j = 0; j < 32; j += 8) {
        int r = r0 + threadIdx.y + j;
        tile[threadIdx.y + j][threadIdx.x] = s[(size_t)r * C + c];
    }
    __syncthreads();
    int rr = r0 + threadIdx.x;   // output column (= source row)
    #pragma unroll
    for (int j = 0; j < 32; j += 8) {
        int cc = c0 + threadIdx.y + j;  // output row (= source column)
        d[(size_t)cc * R + rr] = tile[threadIdx.x][threadIdx.y + j];
    }
}

// ---------------- top-3 NN + weights ----------------
// query xyz: [B, N, 3]; coarse prep in g_s4 [B, S]; writes g_idx/g_w at (b*N+n)*3
__global__ void topk_kernel(const float* __restrict__ xyzq, int N, int S) {
    __shared__ float4 sh[N1];   // max S = 2048 -> 32KB
    int bpb = N / blockDim.x;
    int b   = blockIdx.x / bpb;
    int n   = (blockIdx.x % bpb) * blockDim.x + threadIdx.x;

    const float4* s4b = g_s4 + b * S;
    for (int i = threadIdx.x; i < S; i += blockDim.x) sh[i] = s4b[i];
    __syncthreads();

    const float* q = xyzq + ((size_t)b * N + n) * 3;
    float qx = q[0], qy = q[1], qz = q[2];

    float b0 = 1e30f, b1 = 1e30f, b2 = 1e30f;
    int   i0 = 0, i1 = 0, i2 = 0;

    #pragma unroll 4
    for (int s = 0; s < S; ++s) {
        float4 p = sh[s];
        float e = fmaf(qx, p.x, fmaf(qy, p.y, fmaf(qz, p.z, p.w)));
        if (e < b2) {
            if (e < b0)      { b2 = b1; i2 = i1; b1 = b0; i1 = i0; b0 = e; i0 = s; }
            else if (e < b1) { b2 = b1; i2 = i1; b1 = e;  i1 = s; }
            else             { b2 = e;  i2 = s; }
        }
    }

    float cn = qx * qx + qy * qy + qz * qz;
    float d0 = cn + b0, d1 = cn + b1, d2 = cn + b2;
    float r0 = 1.f / (d0 + 1e-8f);
    float r1 = 1.f / (d1 + 1e-8f);
    float r2 = 1.f / (d2 + 1e-8f);
    float inv = 1.f / (r0 + r1 + r2);

    size_t o = ((size_t)b * N + n) * 3;
    g_idx[o] = i0; g_idx[o + 1] = i1; g_idx[o + 2] = i2;
    g_w[o]   = r0 * inv; g_w[o + 1] = r1 * inv; g_w[o + 2] = r2 * inv;
}

// ---------------- stage-1 interp + concat -> g_inter [B, N1, 768] point-major ----------------
__global__ void interp1_kernel(const float* __restrict__ x1 /*[B,256,2048]*/) {
    int bn = blockIdx.x;            // b*N1 + n
    int b  = bn / N1;
    int n  = bn % N1;
    size_t o = (size_t)bn * 3;
    int   i0 = g_idx[o], i1 = g_idx[o + 1], i2 = g_idx[o + 2];
    float w0 = g_w[o],   w1 = g_w[o + 1],   w2 = g_w[o + 2];

    float* dst = g_inter + (size_t)bn * DI;

    // part A: transpose x1 row (256 threads == D1C)
    int d = threadIdx.x;
    dst[d] = x1[((size_t)b * D1C + d) * N1 + n];

    // part B: gather from x2t [B, S, D2C]
    const float* base = g_x2t + (size_t)b * N2 * D2C;
    const float* r0 = base + (size_t)i0 * D2C;
    const float* r1 = base + (size_t)i1 * D2C;
    const float* r2 = base + (size_t)i2 * D2C;
    #pragma unroll
    for (int dd = threadIdx.x; dd < D2C; dd += 256)
        dst[D1C + dd] = w0 * r0[dd] + w1 * r1[dd] + w2 * r2[dd];
}

// ---------------- copy x0 into out[:, 0:128, :] ----------------
__global__ void copy_x0_kernel(const float* __restrict__ x0, float* __restrict__ out) {
    const int per_b = D0 * N0 / 4;          // float4s per batch
    int i = blockIdx.x * blockDim.x + threadIdx.x;
    if (i < B * per_b) {
        int b = i / per_b, r = i % per_b;
        reinterpret_cast<float4*>(out)[(size_t)b * (DT * N0 / 4) + r] =
            reinterpret_cast<const float4*>(x0)[i];
    }
}

// ---------------- stage-2 interp: out[:, 128:896, :] from g_inter ----------------
// block = 256 threads, handles 32 points x all 768 features in 64-wide chunks
__global__ void interp2_kernel(float* __restrict__ out) {
    __shared__ float acc[32 * 65];
    __shared__ int   sidx[32 * 3];
    __shared__ float sw[32 * 3];

    int b  = blockIdx.x / (N0 / 32);
    int n0 = (blockIdx.x % (N0 / 32)) * 32;
    int t  = threadIdx.x;

    if (t < 96) {
        size_t o = ((size_t)b * N0 + n0) * 3 + t;
        sidx[t] = g_idx[o];
        sw[t]   = g_w[o];
    }
    __syncthreads();

    const float* interb = g_inter + (size_t)b * N1 * DI;
    float* outb = out + (size_t)b * DT * N0;

    for (int d0 = 0; d0 < DI; d0 += 64) {
        // gather-accumulate: consecutive threads -> consecutive dd (coalesced row chunks)
        #pragma unroll
        for (int e = t; e < 32 * 64; e += 256) {
            int p  = e >> 6;
            int dd = e & 63;
            int base = p * 3;
            float v = sw[base]     * interb[(size_t)sidx[base]     * DI + d0 + dd]
                    + sw[base + 1] * interb[(size_t)sidx[base + 1] * DI + d0 + dd]
                    + sw[base + 2] * interb[(size_t)sidx[base + 2] * DI + d0 + dd];
            acc[p * 65 + dd] = v;
        }
        __syncthreads();
        // write: consecutive threads -> consecutive n (coalesced), stride-65 smem (conflict-free)
        #pragma unroll
        for (int e = t; e < 32 * 64; e += 256) {
            int dd = e >> 5;
            int p  = e & 31;
            outb[(size_t)(D0 + d0 + dd) * N0 + n0 + p] = acc[p * 65 + dd];
        }
        __syncthreads();
    }
}

// ---------------- launch ----------------
extern "C" void kernel_launch(void* const* d_in, const int* in_sizes, int n_in,
                              void* d_out, int out_size) {
    const float* xyz0 = (const float*)d_in[0];  // [4,8192,3]
    const float* xyz1 = (const float*)d_in[1];  // [4,2048,3]
    const float* xyz2 = (const float*)d_in[2];  // [4,512,3]
    const float* x0   = (const float*)d_in[3];  // [4,128,8192]
    const float* x1   = (const float*)d_in[4];  // [4,256,2048]
    const float* x2   = (const float*)d_in[5];  // [4,512,512]
    float* out = (float*)d_out;

    float* x2t_ptr;
    cudaGetSymbolAddress((void**)&x2t_ptr, g_x2t);

    // stage 1
    prep_kernel<<<(B * N2 + 255) / 256, 256>>>(xyz2, B * N2);
    {
        float* dst = x2t_ptr;
        dim3 grid(N2 / 32, D2C / 32, B), blk(32, 8);
        transpose_kernel<<<grid, blk>>>(x2, dst, D2C, N2);
    }
    topk_kernel<<<B * N1 / 256, 256>>>(xyz1, N1, N2);
    interp1_kernel<<<B * N1, 256>>>(x1);

    // stage 2
    prep_kernel<<<(B * N1 + 255) / 256, 256>>>(xyz1, B * N1);
    topk_kernel<<<B * N0 / 256, 256>>>(xyz0, N0, N1);
    copy_x0_kernel<<<(B * D0 * N0 / 4 + 255) / 256, 256>>>(x0, out);
    interp2_kernel<<<B * (N0 / 32), 256>>>(out);
}

// round 5
// speedup vs baseline: 1.0139x; 1.0139x over previous
#include <cuda_runtime.h>
#include <math.h>

// ---------------- problem constants ----------------
#define B   4
#define N0  8192   // finest
#define N1  2048
#define N2  512    // coarsest
#define D0  128    // x0 channels
#define D1C 256    // x1 channels
#define D2C 512    // x2 channels
#define DI  768    // intermediate channels (D1C + D2C)
#define DT  896    // output channels (D0 + DI)

// ---------------- scratch (device globals; no allocation allowed) ----------------
__device__ float4 g_s4a[B * N2];           // prepped xyz2
__device__ float4 g_s4b[B * N1];           // prepped xyz1
__device__ float  g_x2t[B * N2 * D2C];     // x2 transposed to [B, S, D]
__device__ float  g_inter[B * N1 * DI];    // stage-1 result, point-major [B, N1, 768]
__device__ int    g_idx1[B * N1 * 3];
__device__ float  g_w1[B * N1 * 3];
__device__ int    g_idx2[B * N0 * 3];
__device__ float  g_w2[B * N0 * 3];

// ---------------- prep both coarse sets: p -> (-2x,-2y,-2z,|p|^2) ----------------
__global__ void prep_both_kernel(const float* __restrict__ xyz2,
                                 const float* __restrict__ xyz1) {
    int i = blockIdx.x * blockDim.x + threadIdx.x;
    if (i < B * N2) {
        float x = xyz2[3 * i], y = xyz2[3 * i + 1], z = xyz2[3 * i + 2];
        g_s4a[i] = make_float4(-2.f * x, -2.f * y, -2.f * z, x * x + y * y + z * z);
    } else if (i < B * N2 + B * N1) {
        int j = i - B * N2;
        float x = xyz1[3 * j], y = xyz1[3 * j + 1], z = xyz1[3 * j + 2];
        g_s4b[j] = make_float4(-2.f * x, -2.f * y, -2.f * z, x * x + y * y + z * z);
    }
}

// ---------------- transpose [B,R,C] -> dst rows of length >= R at given strides ----
// dst[b*dbstride + c*dstride + r] = src[b*R*C + r*C + c]
__global__ void transpose_kernel(const float* __restrict__ src, float* __restrict__ dst,
                                 int R, int C, int dstride, int dbstride) {
    __shared__ float tile[32][33];
    int b  = blockIdx.z;
    int c0 = blockIdx.x * 32, r0 = blockIdx.y * 32;
    const float* s = src + (size_t)b * R * C;
    float*       d = dst + (size_t)b * dbstride;
    int c = c0 + threadIdx.x;
    #pragma unroll
    for (int j = 0; j < 32; j += 8) {
        int r = r0 + threadIdx.y + j;
        tile[threadIdx.y + j][threadIdx.x] = s[(size_t)r * C + c];
    }
    __syncthreads();
    int rr = r0 + threadIdx.x;   // output minor index (= source row)
    #pragma unroll
    for (int j = 0; j < 32; j += 8) {
        int cc = c0 + threadIdx.y + j;  // output row (= source column)
        d[(size_t)cc * dstride + rr] = tile[threadIdx.x][threadIdx.y + j];
    }
}

// ---------------- top-3 NN + weights (64-thread blocks) ----------------
__global__ void topk_kernel(const float* __restrict__ xyzq, const float4* __restrict__ s4,
                            int N, int S, int* __restrict__ idx, float* __restrict__ w) {
    extern __shared__ float4 sh[];
    int bpb = N / 64;
    int b   = blockIdx.x / bpb;
    int n   = (blockIdx.x % bpb) * 64 + threadIdx.x;

    const float4* s4b = s4 + b * S;
    for (int i = threadIdx.x; i < S; i += 64) sh[i] = s4b[i];
    __syncthreads();

    const float* q = xyzq + ((size_t)b * N + n) * 3;
    float qx = q[0], qy = q[1], qz = q[2];

    float b0 = 1e30f, b1 = 1e30f, b2 = 1e30f;
    int   i0 = 0, i1 = 0, i2 = 0;

#define INS(E, SS)                                                          \
    if ((E) < b2) {                                                         \
        if ((E) < b0)      { b2 = b1; i2 = i1; b1 = b0; i1 = i0; b0 = (E); i0 = (SS); } \
        else if ((E) < b1) { b2 = b1; i2 = i1; b1 = (E); i1 = (SS); }       \
        else               { b2 = (E); i2 = (SS); }                         \
    }

    #pragma unroll 2
    for (int s = 0; s < S; s += 2) {
        float4 p0 = sh[s];
        float4 p1 = sh[s + 1];
        float e0 = fmaf(qx, p0.x, fmaf(qy, p0.y, fmaf(qz, p0.z, p0.w)));
        float e1 = fmaf(qx, p1.x, fmaf(qy, p1.y, fmaf(qz, p1.z, p1.w)));
        if (fminf(e0, e1) < b2) {
            INS(e0, s);
            INS(e1, s + 1);
        }
    }
#undef INS

    float cn = qx * qx + qy * qy + qz * qz;
    float d0 = cn + b0, d1 = cn + b1, d2 = cn + b2;
    float r0 = 1.f / (d0 + 1e-8f);
    float r1 = 1.f / (d1 + 1e-8f);
    float r2 = 1.f / (d2 + 1e-8f);
    float inv = 1.f / (r0 + r1 + r2);

    size_t o = ((size_t)b * N + n) * 3;
    idx[o] = i0; idx[o + 1] = i1; idx[o + 2] = i2;
    w[o]   = r0 * inv; w[o + 1] = r1 * inv; w[o + 2] = r2 * inv;
}

// ---------------- stage-1 gather: g_inter[:, 256:768] from g_x2t ----------------
// 32 points per block, 256 threads; dst point-major -> coalesced direct stores
__global__ void gather1_kernel() {
    __shared__ int   sidx[32 * 3];
    __shared__ float sw[32 * 3];

    int b  = blockIdx.x / (N1 / 32);
    int n0 = (blockIdx.x % (N1 / 32)) * 32;
    int t  = threadIdx.x;

    if (t < 96) {
        size_t o = ((size_t)b * N1 + n0) * 3 + t;
        sidx[t] = g_idx1[o];
        sw[t]   = g_w1[o];
    }
    __syncthreads();

    const float* xb  = g_x2t + (size_t)b * N2 * D2C;
    float* dstb = g_inter + ((size_t)b * N1 + n0) * DI + D1C;

    #pragma unroll
    for (int d0 = 0; d0 < D2C; d0 += 64) {
        #pragma unroll
        for (int e = t; e < 32 * 64; e += 256) {
            int p  = e >> 6;
            int dd = e & 63;
            int base = p * 3;
            float v = sw[base]     * xb[(size_t)sidx[base]     * D2C + d0 + dd]
                    + sw[base + 1] * xb[(size_t)sidx[base + 1] * D2C + d0 + dd]
                    + sw[base + 2] * xb[(size_t)sidx[base + 2] * D2C + d0 + dd];
            dstb[(size_t)p * DI + d0 + dd] = v;
        }
    }
}

// ---------------- stage-2: out[:, 0:128] copy + out[:, 128:896] interp ----------------
__global__ void interp2_kernel(const float* __restrict__ x0, float* __restrict__ out) {
    __shared__ float acc[32 * 65];
    __shared__ int   sidx[32 * 3];
    __shared__ float sw[32 * 3];

    int b  = blockIdx.x / (N0 / 32);
    int n0 = (blockIdx.x % (N0 / 32)) * 32;
    int t  = threadIdx.x;

    if (t < 96) {
        size_t o = ((size_t)b * N0 + n0) * 3 + t;
        sidx[t] = g_idx2[o];
        sw[t]   = g_w2[o];
    }

    // channels 0..128: straight copy of x0, float4 over n (no smem needed)
    {
        const float4* x04 = reinterpret_cast<const float4*>(x0) + (size_t)b * D0 * (N0 / 4);
        float4*       o4  = reinterpret_cast<float4*>(out)      + (size_t)b * DT * (N0 / 4);
        int q0 = n0 / 4;
        #pragma unroll
        for (int e = t; e < D0 * 8; e += 256) {
            int dd = e >> 3;     // channel
            int q  = e & 7;      // float4 within the 32-point chunk
            o4[(size_t)dd * (N0 / 4) + q0 + q] = x04[(size_t)dd * (N0 / 4) + q0 + q];
        }
    }
    __syncthreads();

    const float* interb = g_inter + (size_t)b * N1 * DI;
    float* outb = out + (size_t)b * DT * N0;

    for (int d0 = 0; d0 < DI; d0 += 64) {
        // gather-accumulate: coalesced 128B row chunks from g_inter
        #pragma unroll
        for (int e = t; e < 32 * 64; e += 256) {
            int p  = e >> 6;
            int dd = e & 63;
            int base = p * 3;
            float v = sw[base]     * interb[(size_t)sidx[base]     * DI + d0 + dd]
                    + sw[base + 1] * interb[(size_t)sidx[base + 1] * DI + d0 + dd]
                    + sw[base + 2] * interb[(size_t)sidx[base + 2] * DI + d0 + dd];
            acc[p * 65 + dd] = v;
        }
        __syncthreads();
        // write transposed: consecutive threads -> consecutive n (coalesced)
        #pragma unroll
        for (int e = t; e < 32 * 64; e += 256) {
            int dd = e >> 5;
            int p  = e & 31;
            outb[(size_t)(D0 + d0 + dd) * N0 + n0 + p] = acc[p * 65 + dd];
        }
        __syncthreads();
    }
}

// ---------------- launch ----------------
extern "C" void kernel_launch(void* const* d_in, const int* in_sizes, int n_in,
                              void* d_out, int out_size) {
    const float* xyz0 = (const float*)d_in[0];  // [4,8192,3]
    const float* xyz1 = (const float*)d_in[1];  // [4,2048,3]
    const float* xyz2 = (const float*)d_in[2];  // [4,512,3]
    const float* x0   = (const float*)d_in[3];  // [4,128,8192]
    const float* x1   = (const float*)d_in[4];  // [4,256,2048]
    const float* x2   = (const float*)d_in[5];  // [4,512,512]
    float* out = (float*)d_out;

    float* x2t_ptr;   cudaGetSymbolAddress((void**)&x2t_ptr, g_x2t);
    float* inter_ptr; cudaGetSymbolAddress((void**)&inter_ptr, g_inter);
    float4* s4a_ptr;  cudaGetSymbolAddress((void**)&s4a_ptr, g_s4a);
    float4* s4b_ptr;  cudaGetSymbolAddress((void**)&s4b_ptr, g_s4b);
    int* idx1_ptr;    cudaGetSymbolAddress((void**)&idx1_ptr, g_idx1);
    float* w1_ptr;    cudaGetSymbolAddress((void**)&w1_ptr, g_w1);
    int* idx2_ptr;    cudaGetSymbolAddress((void**)&idx2_ptr, g_idx2);
    float* w2_ptr;    cudaGetSymbolAddress((void**)&w2_ptr, g_w2);

    // prep both coarse sets (one launch)
    prep_both_kernel<<<(B * (N2 + N1) + 255) / 256, 256>>>(xyz2, xyz1);

    // x2 -> g_x2t [B, 512, 512]
    {
        dim3 grid(N2 / 32, D2C / 32, B), blk(32, 8);
        transpose_kernel<<<grid, blk>>>(x2, x2t_ptr, D2C, N2, D2C, N2 * D2C);
    }
    // x1 -> g_inter[:, :, 0:256]  (coalesced transpose instead of strided gather)
    {
        dim3 grid(N1 / 32, D1C / 32, B), blk(32, 8);
        transpose_kernel<<<grid, blk>>>(x1, inter_ptr, D1C, N1, DI, N1 * DI);
    }

    // stage-1 top-3 (S=512) and gather into g_inter[:, :, 256:768]
    topk_kernel<<<B * N1 / 64, 64, N2 * sizeof(float4)>>>(xyz1, s4a_ptr, N1, N2, idx1_ptr, w1_ptr);
    gather1_kernel<<<B * (N1 / 32), 256>>>();

    // stage-2 top-3 (S=2048), then fused copy + interpolate into out
    topk_kernel<<<B * N0 / 64, 64, N1 * sizeof(float4)>>>(xyz0, s4b_ptr, N0, N1, idx2_ptr, w2_ptr);
    interp2_kernel<<<B * (N0 / 32), 256>>>(x0, out);
}

// round 8
// speedup vs baseline: 1.1121x; 1.0969x over previous
#include <cuda_runtime.h>
#include <math.h>

// ---------------- problem constants ----------------
#define B   4
#define N0  8192   // finest
#define N1  2048
#define N2  512    // coarsest
#define D0  128    // x0 channels
#define D1C 256    // x1 channels
#define D2C 512    // x2 channels
#define DI  768    // intermediate channels (D1C + D2C)
#define DT  896    // output channels (D0 + DI)

// ---------------- scratch (device globals; no allocation allowed) ----------------
__device__ float  g_x2t[B * N2 * D2C];     // x2 transposed to [B, S, D]
__device__ float  g_inter[B * N1 * DI];    // stage-1 result, point-major [B, N1, 768]
__device__ int    g_idx1[B * N1 * 3];
__device__ float  g_w1[B * N1 * 3];
__device__ int    g_idx2[B * N0 * 3];
__device__ float  g_w2[B * N0 * 3];

// ---------------- transpose [B,R,C] -> dst rows of length >= R at given strides ----
// dst[b*dbstride + c*dstride + r] = src[b*R*C + r*C + c]
__global__ void transpose_kernel(const float* __restrict__ src, float* __restrict__ dst,
                                 int R, int C, int dstride, int dbstride) {
    __shared__ float tile[32][33];
    int b  = blockIdx.z;
    int c0 = blockIdx.x * 32, r0 = blockIdx.y * 32;
    const float* s = src + (size_t)b * R * C;
    float*       d = dst + (size_t)b * dbstride;
    int c = c0 + threadIdx.x;
    #pragma unroll
    for (int j = 0; j < 32; j += 8) {
        int r = r0 + threadIdx.y + j;
        tile[threadIdx.y + j][threadIdx.x] = s[(size_t)r * C + c];
    }
    __syncthreads();
    int rr = r0 + threadIdx.x;   // output minor index (= source row)
    #pragma unroll
    for (int j = 0; j < 32; j += 8) {
        int cc = c0 + threadIdx.y + j;  // output row (= source column)
        d[(size_t)cc * dstride + rr] = tile[threadIdx.x][threadIdx.y + j];
    }
}

// ---------------- warp-per-query top-3 NN + weights ----------------
// blockDim.x = 1024 (32 warps = 32 queries per block).
// Lane l scans candidates l, l+32, ... keeping a private top-3, then a
// shfl_xor butterfly merges the 32 lane-lists (all lanes converge to the
// global top-3 because the union's smallest 3 values are unique).
#define INS(E, SS)                                                                      \
    if ((E) < b2) {                                                                     \
        if ((E) < b0)      { b2 = b1; i2 = i1; b1 = b0; i1 = i0; b0 = (E); i0 = (SS); } \
        else if ((E) < b1) { b2 = b1; i2 = i1; b1 = (E); i1 = (SS); }                   \
        else               { b2 = (E); i2 = (SS); }                                     \
    }

__global__ void topk_warp_kernel(const float* __restrict__ xyzq,
                                 const float* __restrict__ xyzs,
                                 int N, int S,
                                 int* __restrict__ idx, float* __restrict__ w) {
    extern __shared__ float4 sh[];
    const int qpb  = blockDim.x >> 5;                 // queries per block (32)
    int b    = blockIdx.x / (N / qpb);
    int n    = (blockIdx.x % (N / qpb)) * qpb + (threadIdx.x >> 5);
    int lane = threadIdx.x & 31;

    // build prepped tile (-2x,-2y,-2z,|p|^2) straight from coarse xyz
    const float* sb = xyzs + (size_t)b * S * 3;
    for (int i = threadIdx.x; i < S; i += blockDim.x) {
        float x = sb[3 * i], y = sb[3 * i + 1], z = sb[3 * i + 2];
        sh[i] = make_float4(-2.f * x, -2.f * y, -2.f * z, x * x + y * y + z * z);
    }
    __syncthreads();

    const float* q = xyzq + ((size_t)b * N + n) * 3;
    float qx = q[0], qy = q[1], qz = q[2];

    float b0 = 1e30f, b1 = 1e30f, b2 = 1e30f;
    int   i0 = 0, i1 = 0, i2 = 0;

    #pragma unroll 4
    for (int s = lane; s < S; s += 32) {
        float4 p = sh[s];
        float e = fmaf(qx, p.x, fmaf(qy, p.y, fmaf(qz, p.z, p.w)));
        INS(e, s);
    }

    // butterfly merge of per-lane top-3 lists
    #pragma unroll
    for (int off = 16; off > 0; off >>= 1) {
        float c0 = __shfl_xor_sync(0xffffffffu, b0, off);
        float c1 = __shfl_xor_sync(0xffffffffu, b1, off);
        float c2 = __shfl_xor_sync(0xffffffffu, b2, off);
        int   j0 = __shfl_xor_sync(0xffffffffu, i0, off);
        int   j1 = __shfl_xor_sync(0xffffffffu, i1, off);
        int   j2 = __shfl_xor_sync(0xffffffffu, i2, off);
        INS(c0, j0);
        INS(c1, j1);
        INS(c2, j2);
    }

    if (lane == 0) {
        float cn = qx * qx + qy * qy + qz * qz;
        float d0 = cn + b0, d1 = cn + b1, d2 = cn + b2;
        float r0 = 1.f / (d0 + 1e-8f);
        float r1 = 1.f / (d1 + 1e-8f);
        float r2 = 1.f / (d2 + 1e-8f);
        float inv = 1.f / (r0 + r1 + r2);
        size_t o = ((size_t)b * N + n) * 3;
        idx[o] = i0; idx[o + 1] = i1; idx[o + 2] = i2;
        w[o]   = r0 * inv; w[o + 1] = r1 * inv; w[o + 2] = r2 * inv;
    }
}
#undef INS

// ---------------- stage-1 gather: g_inter[:, 256:768] from g_x2t ----------------
// 32 points per block, 256 threads; dst point-major -> coalesced direct stores
__global__ void gather1_kernel() {
    __shared__ int   sidx[32 * 3];
    __shared__ float sw[32 * 3];

    int b  = blockIdx.x / (N1 / 32);
    int n0 = (blockIdx.x % (N1 / 32)) * 32;
    int t  = threadIdx.x;

    if (t < 96) {
        size_t o = ((size_t)b * N1 + n0) * 3 + t;
        sidx[t] = g_idx1[o];
        sw[t]   = g_w1[o];
    }
    __syncthreads();

    const float* xb  = g_x2t + (size_t)b * N2 * D2C;
    float* dstb = g_inter + ((size_t)b * N1 + n0) * DI + D1C;

    #pragma unroll
    for (int d0 = 0; d0 < D2C; d0 += 64) {
        #pragma unroll
        for (int e = t; e < 32 * 64; e += 256) {
            int p  = e >> 6;
            int dd = e & 63;
            int base = p * 3;
            float v = sw[base]     * xb[(size_t)sidx[base]     * D2C + d0 + dd]
                    + sw[base + 1] * xb[(size_t)sidx[base + 1] * D2C + d0 + dd]
                    + sw[base + 2] * xb[(size_t)sidx[base + 2] * D2C + d0 + dd];
            dstb[(size_t)p * DI + d0 + dd] = v;
        }
    }
}

// ---------------- stage-2: out[:, 0:128] copy + out[:, 128:896] interp ----------------
__global__ void interp2_kernel(const float* __restrict__ x0, float* __restrict__ out) {
    __shared__ float acc[32 * 65];
    __shared__ int   sidx[32 * 3];
    __shared__ float sw[32 * 3];

    int b  = blockIdx.x / (N0 / 32);
    int n0 = (blockIdx.x % (N0 / 32)) * 32;
    int t  = threadIdx.x;

    if (t < 96) {
        size_t o = ((size_t)b * N0 + n0) * 3 + t;
        sidx[t] = g_idx2[o];
        sw[t]   = g_w2[o];
    }

    // channels 0..128: straight copy of x0, float4 over n (no smem needed)
    {
        const float4* x04 = reinterpret_cast<const float4*>(x0) + (size_t)b * D0 * (N0 / 4);
        float4*       o4  = reinterpret_cast<float4*>(out)      + (size_t)b * DT * (N0 / 4);
        int q0 = n0 / 4;
        #pragma unroll
        for (int e = t; e < D0 * 8; e += 256) {
            int dd = e >> 3;     // channel
            int q  = e & 7;      // float4 within the 32-point chunk
            o4[(size_t)dd * (N0 / 4) + q0 + q] = x04[(size_t)dd * (N0 / 4) + q0 + q];
        }
    }
    __syncthreads();

    const float* interb = g_inter + (size_t)b * N1 * DI;
    float* outb = out + (size_t)b * DT * N0;

    for (int d0 = 0; d0 < DI; d0 += 64) {
        // gather-accumulate: coalesced 128B row chunks from g_inter
        #pragma unroll
        for (int e = t; e < 32 * 64; e += 256) {
            int p  = e >> 6;
            int dd = e & 63;
            int base = p * 3;
            float v = sw[base]     * interb[(size_t)sidx[base]     * DI + d0 + dd]
                    + sw[base + 1] * interb[(size_t)sidx[base + 1] * DI + d0 + dd]
                    + sw[base + 2] * interb[(size_t)sidx[base + 2] * DI + d0 + dd];
            acc[p * 65 + dd] = v;
        }
        __syncthreads();
        // write transposed: consecutive threads -> consecutive n (coalesced)
        #pragma unroll
        for (int e = t; e < 32 * 64; e += 256) {
            int dd = e >> 5;
            int p  = e & 31;
            outb[(size_t)(D0 + d0 + dd) * N0 + n0 + p] = acc[p * 65 + dd];
        }
        __syncthreads();
    }
}

// ---------------- launch ----------------
extern "C" void kernel_launch(void* const* d_in, const int* in_sizes, int n_in,
                              void* d_out, int out_size) {
    const float* xyz0 = (const float*)d_in[0];  // [4,8192,3]
    const float* xyz1 = (const float*)d_in[1];  // [4,2048,3]
    const float* xyz2 = (const float*)d_in[2];  // [4,512,3]
    const float* x0   = (const float*)d_in[3];  // [4,128,8192]
    const float* x1   = (const float*)d_in[4];  // [4,256,2048]
    const float* x2   = (const float*)d_in[5];  // [4,512,512]
    float* out = (float*)d_out;

    float* x2t_ptr;   cudaGetSymbolAddress((void**)&x2t_ptr, g_x2t);
    float* inter_ptr; cudaGetSymbolAddress((void**)&inter_ptr, g_inter);
    int* idx1_ptr;    cudaGetSymbolAddress((void**)&idx1_ptr, g_idx1);
    float* w1_ptr;    cudaGetSymbolAddress((void**)&w1_ptr, g_w1);
    int* idx2_ptr;    cudaGetSymbolAddress((void**)&idx2_ptr, g_idx2);
    float* w2_ptr;    cudaGetSymbolAddress((void**)&w2_ptr, g_w2);

    // x2 -> g_x2t [B, 512, 512]
    {
        dim3 grid(N2 / 32, D2C / 32, B), blk(32, 8);
        transpose_kernel<<<grid, blk>>>(x2, x2t_ptr, D2C, N2, D2C, N2 * D2C);
    }
    // x1 -> g_inter[:, :, 0:256]  (coalesced transpose instead of strided gather)
    {
        dim3 grid(N1 / 32, D1C / 32, B), blk(32, 8);
        transpose_kernel<<<grid, blk>>>(x1, inter_ptr, D1C, N1, DI, N1 * DI);
    }

    // stage-1 top-3 (N=2048 queries/batch, S=512): 256 blocks x 1024 thr, 8KB tile
    topk_warp_kernel<<<B * N1 / 32, 1024, N2 * sizeof(float4)>>>(
        xyz1, xyz2, N1, N2, idx1_ptr, w1_ptr);
    gather1_kernel<<<B * (N1 / 32), 256>>>();

    // stage-2 top-3 (N=8192 queries/batch, S=2048): 1024 blocks x 1024 thr, 32KB tile
    topk_warp_kernel<<<B * N0 / 32, 1024, N1 * sizeof(float4)>>>(
        xyz0, xyz1, N0, N1, idx2_ptr, w2_ptr);

    // fused copy + interpolate into out
    interp2_kernel<<<B * (N0 / 32), 256>>>(x0, out);
}

// round 9
// speedup vs baseline: 1.3520x; 1.2157x over previous
#include <cuda_runtime.h>
#include <math.h>

// ---------------- problem constants ----------------
#define B   4
#define N0  8192   // finest
#define N1  2048
#define N2  512    // coarsest
#define D0  128    // x0 channels
#define D1C 256    // x1 channels
#define D2C 512    // x2 channels
#define DI  768    // intermediate channels (D1C + D2C)
#define DT  896    // output channels (D0 + DI)

// ---------------- scratch (device globals; no allocation allowed) ----------------
__device__ float  g_x2t[B * N2 * D2C];     // x2 transposed to [B, S, D]
__device__ float  g_inter[B * N1 * DI];    // stage-1 result, point-major [B, N1, 768]
__device__ int    g_idx1[B * N1 * 3];
__device__ float  g_w1[B * N1 * 3];
__device__ int    g_idx2[B * N0 * 3];
__device__ float  g_w2[B * N0 * 3];

// ---------------- transpose [B,R,C] -> dst rows of length >= R at given strides ----
// dst[b*dbstride + c*dstride + r] = src[b*R*C + r*C + c]
__global__ void transpose_kernel(const float* __restrict__ src, float* __restrict__ dst,
                                 int R, int C, int dstride, int dbstride) {
    __shared__ float tile[32][33];
    int b  = blockIdx.z;
    int c0 = blockIdx.x * 32, r0 = blockIdx.y * 32;
    const float* s = src + (size_t)b * R * C;
    float*       d = dst + (size_t)b * dbstride;
    int c = c0 + threadIdx.x;
    #pragma unroll
    for (int j = 0; j < 32; j += 8) {
        int r = r0 + threadIdx.y + j;
        tile[threadIdx.y + j][threadIdx.x] = s[(size_t)r * C + c];
    }
    __syncthreads();
    int rr = r0 + threadIdx.x;   // output minor index (= source row)
    #pragma unroll
    for (int j = 0; j < 32; j += 8) {
        int cc = c0 + threadIdx.y + j;  // output row (= source column)
        d[(size_t)cc * dstride + rr] = tile[threadIdx.x][threadIdx.y + j];
    }
}

// ---------------- warp-per-query top-3 NN + weights ----------------
// blockDim.x = 1024 (32 warps = 32 queries per block).
// Lane l scans candidates l, l+32, ... keeping a private top-3, then a
// shfl_xor butterfly merges the 32 lane-lists.
#define INS(E, SS)                                                                      \
    if ((E) < b2) {                                                                     \
        if ((E) < b0)      { b2 = b1; i2 = i1; b1 = b0; i1 = i0; b0 = (E); i0 = (SS); } \
        else if ((E) < b1) { b2 = b1; i2 = i1; b1 = (E); i1 = (SS); }                   \
        else               { b2 = (E); i2 = (SS); }                                     \
    }

__global__ void topk_warp_kernel(const float* __restrict__ xyzq,
                                 const float* __restrict__ xyzs,
                                 int N, int S,
                                 int* __restrict__ idx, float* __restrict__ w) {
    extern __shared__ float4 sh[];
    const int qpb  = blockDim.x >> 5;                 // queries per block (32)
    int b    = blockIdx.x / (N / qpb);
    int n    = (blockIdx.x % (N / qpb)) * qpb + (threadIdx.x >> 5);
    int lane = threadIdx.x & 31;

    // build prepped tile (-2x,-2y,-2z,|p|^2) straight from coarse xyz
    const float* sb = xyzs + (size_t)b * S * 3;
    for (int i = threadIdx.x; i < S; i += blockDim.x) {
        float x = sb[3 * i], y = sb[3 * i + 1], z = sb[3 * i + 2];
        sh[i] = make_float4(-2.f * x, -2.f * y, -2.f * z, x * x + y * y + z * z);
    }
    __syncthreads();

    const float* q = xyzq + ((size_t)b * N + n) * 3;
    float qx = q[0], qy = q[1], qz = q[2];

    float b0 = 1e30f, b1 = 1e30f, b2 = 1e30f;
    int   i0 = 0, i1 = 0, i2 = 0;

    #pragma unroll 4
    for (int s = lane; s < S; s += 32) {
        float4 p = sh[s];
        float e = fmaf(qx, p.x, fmaf(qy, p.y, fmaf(qz, p.z, p.w)));
        INS(e, s);
    }

    // butterfly merge of per-lane top-3 lists
    #pragma unroll
    for (int off = 16; off > 0; off >>= 1) {
        float c0 = __shfl_xor_sync(0xffffffffu, b0, off);
        float c1 = __shfl_xor_sync(0xffffffffu, b1, off);
        float c2 = __shfl_xor_sync(0xffffffffu, b2, off);
        int   j0 = __shfl_xor_sync(0xffffffffu, i0, off);
        int   j1 = __shfl_xor_sync(0xffffffffu, i1, off);
        int   j2 = __shfl_xor_sync(0xffffffffu, i2, off);
        INS(c0, j0);
        INS(c1, j1);
        INS(c2, j2);
    }

    if (lane == 0) {
        float cn = qx * qx + qy * qy + qz * qz;
        float d0 = cn + b0, d1 = cn + b1, d2 = cn + b2;
        float r0 = 1.f / (d0 + 1e-8f);
        float r1 = 1.f / (d1 + 1e-8f);
        float r2 = 1.f / (d2 + 1e-8f);
        float inv = 1.f / (r0 + r1 + r2);
        size_t o = ((size_t)b * N + n) * 3;
        idx[o] = i0; idx[o + 1] = i1; idx[o + 2] = i2;
        w[o]   = r0 * inv; w[o + 1] = r1 * inv; w[o + 2] = r2 * inv;
    }
}
#undef INS

// ---------------- stage-1 gather (split): g_inter[:, 256:768] from g_x2t ----------------
// grid (B*N1/32, D2C/64): one 32-point x 64-channel tile per block, 256 threads.
__global__ __launch_bounds__(256) void gather1_kernel() {
    __shared__ int   sidx[32 * 3];
    __shared__ float sw[32 * 3];

    int b  = blockIdx.x / (N1 / 32);
    int n0 = (blockIdx.x % (N1 / 32)) * 32;
    int d0 = blockIdx.y * 64;
    int t  = threadIdx.x;

    if (t < 96) {
        size_t o = ((size_t)b * N1 + n0) * 3 + t;
        sidx[t] = g_idx1[o];
        sw[t]   = g_w1[o];
    }
    __syncthreads();

    const float* xb = g_x2t + (size_t)b * N2 * D2C + d0;
    float* dstb = g_inter + ((size_t)b * N1 + n0) * DI + D1C + d0;

    #pragma unroll
    for (int e = t; e < 32 * 64; e += 256) {
        int p  = e >> 6;
        int dd = e & 63;
        int base = p * 3;
        float v = sw[base]     * xb[(size_t)sidx[base]     * D2C + dd]
                + sw[base + 1] * xb[(size_t)sidx[base + 1] * D2C + dd]
                + sw[base + 2] * xb[(size_t)sidx[base + 2] * D2C + dd];
        dstb[(size_t)p * DI + dd] = v;
    }
}

// ---------------- stage-2 (split): out[:, 0:128] copy + out[:, 128:896] interp ----
// grid (B*N0/32, 13): y<12 -> interp chunk d0=y*64; y==12 -> x0 copy.
__global__ __launch_bounds__(256) void interp2_kernel(const float* __restrict__ x0,
                                                      float* __restrict__ out) {
    __shared__ float acc[32 * 65];
    __shared__ int   sidx[32 * 3];
    __shared__ float sw[32 * 3];

    int b  = blockIdx.x / (N0 / 32);
    int n0 = (blockIdx.x % (N0 / 32)) * 32;
    int t  = threadIdx.x;

    if (blockIdx.y == 12) {
        // channels 0..128: straight copy of x0, float4 over n
        const float4* x04 = reinterpret_cast<const float4*>(x0) + (size_t)b * D0 * (N0 / 4);
        float4*       o4  = reinterpret_cast<float4*>(out)      + (size_t)b * DT * (N0 / 4);
        int q0 = n0 / 4;
        #pragma unroll
        for (int e = t; e < D0 * 8; e += 256) {
            int dd = e >> 3;     // channel
            int q  = e & 7;      // float4 within the 32-point chunk
            o4[(size_t)dd * (N0 / 4) + q0 + q] = x04[(size_t)dd * (N0 / 4) + q0 + q];
        }
        return;
    }

    int d0 = blockIdx.y * 64;

    if (t < 96) {
        size_t o = ((size_t)b * N0 + n0) * 3 + t;
        sidx[t] = g_idx2[o];
        sw[t]   = g_w2[o];
    }
    __syncthreads();

    const float* interb = g_inter + (size_t)b * N1 * DI + d0;
    float* outb = out + (size_t)b * DT * N0 + (size_t)(D0 + d0) * N0 + n0;

    // gather-accumulate: coalesced 256B row chunks from g_inter
    #pragma unroll
    for (int e = t; e < 32 * 64; e += 256) {
        int p  = e >> 6;
        int dd = e & 63;
        int base = p * 3;
        float v = sw[base]     * interb[(size_t)sidx[base]     * DI + dd]
                + sw[base + 1] * interb[(size_t)sidx[base + 1] * DI + dd]
                + sw[base + 2] * interb[(size_t)sidx[base + 2] * DI + dd];
        acc[p * 65 + dd] = v;
    }
    __syncthreads();
    // write transposed: consecutive threads -> consecutive n (coalesced)
    #pragma unroll
    for (int e = t; e < 32 * 64; e += 256) {
        int dd = e >> 5;
        int p  = e & 31;
        outb[(size_t)dd * N0 + p] = acc[p * 65 + dd];
    }
}

// ---------------- launch ----------------
extern "C" void kernel_launch(void* const* d_in, const int* in_sizes, int n_in,
                              void* d_out, int out_size) {
    const float* xyz0 = (const float*)d_in[0];  // [4,8192,3]
    const float* xyz1 = (const float*)d_in[1];  // [4,2048,3]
    const float* xyz2 = (const float*)d_in[2];  // [4,512,3]
    const float* x0   = (const float*)d_in[3];  // [4,128,8192]
    const float* x1   = (const float*)d_in[4];  // [4,256,2048]
    const float* x2   = (const float*)d_in[5];  // [4,512,512]
    float* out = (float*)d_out;

    float* x2t_ptr;   cudaGetSymbolAddress((void**)&x2t_ptr, g_x2t);
    float* inter_ptr; cudaGetSymbolAddress((void**)&inter_ptr, g_inter);
    int* idx1_ptr;    cudaGetSymbolAddress((void**)&idx1_ptr, g_idx1);
    float* w1_ptr;    cudaGetSymbolAddress((void**)&w1_ptr, g_w1);
    int* idx2_ptr;    cudaGetSymbolAddress((void**)&idx2_ptr, g_idx2);
    float* w2_ptr;    cudaGetSymbolAddress((void**)&w2_ptr, g_w2);

    // x2 -> g_x2t [B, 512, 512]
    {
        dim3 grid(N2 / 32, D2C / 32, B), blk(32, 8);
        transpose_kernel<<<grid, blk>>>(x2, x2t_ptr, D2C, N2, D2C, N2 * D2C);
    }
    // x1 -> g_inter[:, :, 0:256]  (coalesced transpose instead of strided gather)
    {
        dim3 grid(N1 / 32, D1C / 32, B), blk(32, 8);
        transpose_kernel<<<grid, blk>>>(x1, inter_ptr, D1C, N1, DI, N1 * DI);
    }

    // stage-1 top-3 (N=2048 queries/batch, S=512): 256 blocks x 1024 thr, 8KB tile
    topk_warp_kernel<<<B * N1 / 32, 1024, N2 * sizeof(float4)>>>(
        xyz1, xyz2, N1, N2, idx1_ptr, w1_ptr);

    // stage-1 gather: 2048 blocks (32 pts x 64 ch tiles)
    {
        dim3 grid(B * (N1 / 32), D2C / 64);
        gather1_kernel<<<grid, 256>>>();
    }

    // stage-2 top-3 (N=8192 queries/batch, S=2048): 1024 blocks x 1024 thr, 32KB tile
    topk_warp_kernel<<<B * N0 / 32, 1024, N1 * sizeof(float4)>>>(
        xyz0, xyz1, N0, N1, idx2_ptr, w2_ptr);

    // fused copy + interpolate into out: 13312 blocks
    {
        dim3 grid(B * (N0 / 32), 13);
        interp2_kernel<<<grid, 256>>>(x0, out);
    }
}

// round 10
// speedup vs baseline: 1.7303x; 1.2798x over previous
#include <cuda_runtime.h>
#include <math.h>

// ---------------- problem constants ----------------
#define B   4
#define N0  8192   // finest
#define N1  2048
#define N2  512    // coarsest
#define D0  128    // x0 channels
#define D1C 256    // x1 channels
#define D2C 512    // x2 channels
#define DI  768    // intermediate channels (D1C + D2C)
#define DT  896    // output channels (D0 + DI)

// ---------------- scratch (device globals; no allocation allowed) ----------------
__device__ float  g_x2t[B * N2 * D2C];     // x2 transposed to [B, S, D]
__device__ float  g_inter[B * N1 * DI];    // stage-1 result, point-major [B, N1, 768]
__device__ int    g_idx1[B * N1 * 3];
__device__ float  g_w1[B * N1 * 3];
__device__ int    g_idx2[B * N0 * 3];
__device__ float  g_w2[B * N0 * 3];

// ---------------- transpose [B,R,C] -> dst rows of length >= R at given strides ----
// dst[b*dbstride + c*dstride + r] = src[b*R*C + r*C + c]
__global__ void transpose_kernel(const float* __restrict__ src, float* __restrict__ dst,
                                 int R, int C, int dstride, int dbstride) {
    __shared__ float tile[32][33];
    int b  = blockIdx.z;
    int c0 = blockIdx.x * 32, r0 = blockIdx.y * 32;
    const float* s = src + (size_t)b * R * C;
    float*       d = dst + (size_t)b * dbstride;
    int c = c0 + threadIdx.x;
    #pragma unroll
    for (int j = 0; j < 32; j += 8) {
        int r = r0 + threadIdx.y + j;
        tile[threadIdx.y + j][threadIdx.x] = s[(size_t)r * C + c];
    }
    __syncthreads();
    int rr = r0 + threadIdx.x;   // output minor index (= source row)
    #pragma unroll
    for (int j = 0; j < 32; j += 8) {
        int cc = c0 + threadIdx.y + j;  // output row (= source column)
        d[(size_t)cc * dstride + rr] = tile[threadIdx.x][threadIdx.y + j];
    }
}

#define INS(E, SS)                                                                      \
    if ((E) < b2) {                                                                     \
        if ((E) < b0)      { b2 = b1; i2 = i1; b1 = b0; i1 = i0; b0 = (E); i0 = (SS); } \
        else if ((E) < b1) { b2 = b1; i2 = i1; b1 = (E); i1 = (SS); }                   \
        else               { b2 = (E); i2 = (SS); }                                     \
    }

// ---------------- warp-per-query top-3 (stage 1, S=512) ----------------
__global__ void topk_warp_kernel(const float* __restrict__ xyzq,
                                 const float* __restrict__ xyzs,
                                 int N, int S,
                                 int* __restrict__ idx, float* __restrict__ w) {
    extern __shared__ float4 sh[];
    const int qpb  = blockDim.x >> 5;                 // queries per block (32)
    int b    = blockIdx.x / (N / qpb);
    int n    = (blockIdx.x % (N / qpb)) * qpb + (threadIdx.x >> 5);
    int lane = threadIdx.x & 31;

    const float* sb = xyzs + (size_t)b * S * 3;
    for (int i = threadIdx.x; i < S; i += blockDim.x) {
        float x = sb[3 * i], y = sb[3 * i + 1], z = sb[3 * i + 2];
        sh[i] = make_float4(-2.f * x, -2.f * y, -2.f * z, x * x + y * y + z * z);
    }
    __syncthreads();

    const float* q = xyzq + ((size_t)b * N + n) * 3;
    float qx = q[0], qy = q[1], qz = q[2];

    float b0 = 1e30f, b1 = 1e30f, b2 = 1e30f;
    int   i0 = 0, i1 = 0, i2 = 0;

    #pragma unroll 4
    for (int s = lane; s < S; s += 32) {
        float4 p = sh[s];
        float e = fmaf(qx, p.x, fmaf(qy, p.y, fmaf(qz, p.z, p.w)));
        INS(e, s);
    }

    #pragma unroll
    for (int off = 16; off > 0; off >>= 1) {
        float c0 = __shfl_xor_sync(0xffffffffu, b0, off);
        float c1 = __shfl_xor_sync(0xffffffffu, b1, off);
        float c2 = __shfl_xor_sync(0xffffffffu, b2, off);
        int   j0 = __shfl_xor_sync(0xffffffffu, i0, off);
        int   j1 = __shfl_xor_sync(0xffffffffu, i1, off);
        int   j2 = __shfl_xor_sync(0xffffffffu, i2, off);
        INS(c0, j0);
        INS(c1, j1);
        INS(c2, j2);
    }

    if (lane == 0) {
        float cn = qx * qx + qy * qy + qz * qz;
        float r0 = 1.f / (cn + b0 + 1e-8f);
        float r1 = 1.f / (cn + b1 + 1e-8f);
        float r2 = 1.f / (cn + b2 + 1e-8f);
        float inv = 1.f / (r0 + r1 + r2);
        size_t o = ((size_t)b * N + n) * 3;
        idx[o] = i0; idx[o + 1] = i1; idx[o + 2] = i2;
        w[o]   = r0 * inv; w[o + 1] = r1 * inv; w[o + 2] = r2 * inv;
    }
}

// ---------------- quad-per-query top-3 (stage 2, S=2048) ----------------
// 4 lanes per query, 8 queries per warp, 64 queries per 256-thread block.
// Candidate reads are 8-way broadcast across query-groups -> 8x less LDS traffic.
__global__ __launch_bounds__(256) void topk_quad_kernel(const float* __restrict__ xyzq,
                                                        const float* __restrict__ xyzs,
                                                        int N, int S,
                                                        int* __restrict__ idx,
                                                        float* __restrict__ w) {
    extern __shared__ float4 sh[];
    int b      = blockIdx.x / (N / 64);
    int n_base = (blockIdx.x % (N / 64)) * 64;
    int t    = threadIdx.x;
    int warp = t >> 5;
    int lane = t & 31;
    int g    = lane >> 2;     // query group within warp (0..7)
    int l    = lane & 3;      // lane within quad
    int n    = n_base + warp * 8 + g;

    const float* sb = xyzs + (size_t)b * S * 3;
    for (int i = t; i < S; i += 256) {
        float x = sb[3 * i], y = sb[3 * i + 1], z = sb[3 * i + 2];
        sh[i] = make_float4(-2.f * x, -2.f * y, -2.f * z, x * x + y * y + z * z);
    }
    __syncthreads();

    const float* q = xyzq + ((size_t)b * N + n) * 3;
    float qx = q[0], qy = q[1], qz = q[2];

    float b0 = 1e30f, b1 = 1e30f, b2 = 1e30f;
    int   i0 = 0, i1 = 0, i2 = 0;

    // lane l scans candidates {2l, 2l+1, 2l+8, 2l+9, ...}
    #pragma unroll 4
    for (int s = 2 * l; s < S; s += 8) {
        float4 p0 = sh[s];
        float4 p1 = sh[s + 1];
        float e0 = fmaf(qx, p0.x, fmaf(qy, p0.y, fmaf(qz, p0.z, p0.w)));
        float e1 = fmaf(qx, p1.x, fmaf(qy, p1.y, fmaf(qz, p1.z, p1.w)));
        if (fminf(e0, e1) < b2) {
            INS(e0, s);
            INS(e1, s + 1);
        }
    }

    // merge the 4 lane-lists within the quad
    #pragma unroll
    for (int off = 1; off <= 2; off <<= 1) {
        float c0 = __shfl_xor_sync(0xffffffffu, b0, off);
        float c1 = __shfl_xor_sync(0xffffffffu, b1, off);
        float c2 = __shfl_xor_sync(0xffffffffu, b2, off);
        int   j0 = __shfl_xor_sync(0xffffffffu, i0, off);
        int   j1 = __shfl_xor_sync(0xffffffffu, i1, off);
        int   j2 = __shfl_xor_sync(0xffffffffu, i2, off);
        INS(c0, j0);
        INS(c1, j1);
        INS(c2, j2);
    }

    if (l == 0) {
        float cn = qx * qx + qy * qy + qz * qz;
        float r0 = 1.f / (cn + b0 + 1e-8f);
        float r1 = 1.f / (cn + b1 + 1e-8f);
        float r2 = 1.f / (cn + b2 + 1e-8f);
        float inv = 1.f / (r0 + r1 + r2);
        size_t o = ((size_t)b * N + n) * 3;
        idx[o] = i0; idx[o + 1] = i1; idx[o + 2] = i2;
        w[o]   = r0 * inv; w[o + 1] = r1 * inv; w[o + 2] = r2 * inv;
    }
}
#undef INS

// ---------------- stage-1 gather (split, float4): g_inter[:, 256:768] ----------------
// grid (B*N1/32, D2C/64): one 32-point x 64-channel tile per block, 256 threads.
__global__ __launch_bounds__(256) void gather1_kernel() {
    __shared__ int   sidx[32 * 3];
    __shared__ float sw[32 * 3];

    int b  = blockIdx.x / (N1 / 32);
    int n0 = (blockIdx.x % (N1 / 32)) * 32;
    int d0 = blockIdx.y * 64;
    int t  = threadIdx.x;

    if (t < 96) {
        size_t o = ((size_t)b * N1 + n0) * 3 + t;
        sidx[t] = g_idx1[o];
        sw[t]   = g_w1[o];
    }
    __syncthreads();

    const float* xb = g_x2t + (size_t)b * N2 * D2C + d0;
    float* dstb = g_inter + ((size_t)b * N1 + n0) * DI + D1C + d0;

    // 32 points x 16 float4 chunks = 512 items, 2 per thread
    #pragma unroll
    for (int e = t; e < 32 * 16; e += 256) {
        int p = e >> 4;
        int v = (e & 15) * 4;
        int base = p * 3;
        float w0 = sw[base], w1 = sw[base + 1], w2 = sw[base + 2];
        float4 a = *(const float4*)(xb + (size_t)sidx[base]     * D2C + v);
        float4 c = *(const float4*)(xb + (size_t)sidx[base + 1] * D2C + v);
        float4 d = *(const float4*)(xb + (size_t)sidx[base + 2] * D2C + v);
        float4 r;
        r.x = w0 * a.x + w1 * c.x + w2 * d.x;
        r.y = w0 * a.y + w1 * c.y + w2 * d.y;
        r.z = w0 * a.z + w1 * c.z + w2 * d.z;
        r.w = w0 * a.w + w1 * c.w + w2 * d.w;
        *(float4*)(dstb + (size_t)p * DI + v) = r;
    }
}

// ---------------- stage-2 (split, float4 gather): copy + interp into out ----------
// grid (B*N0/32, 13): y<12 -> interp chunk d0=y*64; y==12 -> x0 copy.
__global__ __launch_bounds__(256) void interp2_kernel(const float* __restrict__ x0,
                                                      float* __restrict__ out) {
    __shared__ float acc[32 * 65];
    __shared__ int   sidx[32 * 3];
    __shared__ float sw[32 * 3];

    int b  = blockIdx.x / (N0 / 32);
    int n0 = (blockIdx.x % (N0 / 32)) * 32;
    int t  = threadIdx.x;

    if (blockIdx.y == 12) {
        const float4* x04 = reinterpret_cast<const float4*>(x0) + (size_t)b * D0 * (N0 / 4);
        float4*       o4  = reinterpret_cast<float4*>(out)      + (size_t)b * DT * (N0 / 4);
        int q0 = n0 / 4;
        #pragma unroll
        for (int e = t; e < D0 * 8; e += 256) {
            int dd = e >> 3;
            int q  = e & 7;
            o4[(size_t)dd * (N0 / 4) + q0 + q] = x04[(size_t)dd * (N0 / 4) + q0 + q];
        }
        return;
    }

    int d0 = blockIdx.y * 64;

    if (t < 96) {
        size_t o = ((size_t)b * N0 + n0) * 3 + t;
        sidx[t] = g_idx2[o];
        sw[t]   = g_w2[o];
    }
    __syncthreads();

    const float* interb = g_inter + (size_t)b * N1 * DI + d0;
    float* outb = out + (size_t)b * DT * N0 + (size_t)(D0 + d0) * N0 + n0;

    // gather-accumulate (float4): 32 points x 16 chunks = 512 items
    #pragma unroll
    for (int e = t; e < 32 * 16; e += 256) {
        int p = e >> 4;
        int v = (e & 15) * 4;
        int base = p * 3;
        float w0 = sw[base], w1 = sw[base + 1], w2 = sw[base + 2];
        float4 a = *(const float4*)(interb + (size_t)sidx[base]     * DI + v);
        float4 c = *(const float4*)(interb + (size_t)sidx[base + 1] * DI + v);
        float4 d = *(const float4*)(interb + (size_t)sidx[base + 2] * DI + v);
        float* ap = acc + p * 65 + v;
        ap[0] = w0 * a.x + w1 * c.x + w2 * d.x;
        ap[1] = w0 * a.y + w1 * c.y + w2 * d.y;
        ap[2] = w0 * a.z + w1 * c.z + w2 * d.z;
        ap[3] = w0 * a.w + w1 * c.w + w2 * d.w;
    }
    __syncthreads();
    // write transposed: consecutive threads -> consecutive n (coalesced)
    #pragma unroll
    for (int e = t; e < 32 * 64; e += 256) {
        int dd = e >> 5;
        int p  = e & 31;
        outb[(size_t)dd * N0 + p] = acc[p * 65 + dd];
    }
}

// ---------------- launch ----------------
extern "C" void kernel_launch(void* const* d_in, const int* in_sizes, int n_in,
                              void* d_out, int out_size) {
    const float* xyz0 = (const float*)d_in[0];  // [4,8192,3]
    const float* xyz1 = (const float*)d_in[1];  // [4,2048,3]
    const float* xyz2 = (const float*)d_in[2];  // [4,512,3]
    const float* x0   = (const float*)d_in[3];  // [4,128,8192]
    const float* x1   = (const float*)d_in[4];  // [4,256,2048]
    const float* x2   = (const float*)d_in[5];  // [4,512,512]
    float* out = (float*)d_out;

    float* x2t_ptr;   cudaGetSymbolAddress((void**)&x2t_ptr, g_x2t);
    float* inter_ptr; cudaGetSymbolAddress((void**)&inter_ptr, g_inter);
    int* idx1_ptr;    cudaGetSymbolAddress((void**)&idx1_ptr, g_idx1);
    float* w1_ptr;    cudaGetSymbolAddress((void**)&w1_ptr, g_w1);
    int* idx2_ptr;    cudaGetSymbolAddress((void**)&idx2_ptr, g_idx2);
    float* w2_ptr;    cudaGetSymbolAddress((void**)&w2_ptr, g_w2);

    // x2 -> g_x2t [B, 512, 512]
    {
        dim3 grid(N2 / 32, D2C / 32, B), blk(32, 8);
        transpose_kernel<<<grid, blk>>>(x2, x2t_ptr, D2C, N2, D2C, N2 * D2C);
    }
    // x1 -> g_inter[:, :, 0:256]
    {
        dim3 grid(N1 / 32, D1C / 32, B), blk(32, 8);
        transpose_kernel<<<grid, blk>>>(x1, inter_ptr, D1C, N1, DI, N1 * DI);
    }

    // stage-1 top-3 (S=512): warp-per-query, 256 blocks x 1024 thr, 8KB tile
    topk_warp_kernel<<<B * N1 / 32, 1024, N2 * sizeof(float4)>>>(
        xyz1, xyz2, N1, N2, idx1_ptr, w1_ptr);

    // stage-1 gather: 2048 blocks (32 pts x 64 ch tiles)
    {
        dim3 grid(B * (N1 / 32), D2C / 64);
        gather1_kernel<<<grid, 256>>>();
    }

    // stage-2 top-3 (S=2048): quad-per-query, 512 blocks x 256 thr, 32KB tile
    topk_quad_kernel<<<B * N0 / 64, 256, N1 * sizeof(float4)>>>(
        xyz0, xyz1, N0, N1, idx2_ptr, w2_ptr);

    // fused copy + interpolate into out: 13312 blocks
    {
        dim3 grid(B * (N0 / 32), 13);
        interp2_kernel<<<grid, 256>>>(x0, out);
    }
}

// round 11
// speedup vs baseline: 2.1113x; 1.2202x over previous
#include <cuda_runtime.h>
#include <cuda_fp16.h>
#include <math.h>

// ---------------- problem constants ----------------
#define B   4
#define N0  8192   // finest
#define N1  2048
#define N2  512    // coarsest
#define D0  128    // x0 channels
#define D1C 256    // x1 channels
#define D2C 512    // x2 channels
#define DI  768    // intermediate channels (D1C + D2C)
#define DT  896    // output channels (D0 + DI)

// ---------------- scratch (device globals; no allocation allowed) ----------------
__device__ float  g_x2t[B * N2 * D2C];                 // x2 transposed, fp32 [B,S,D]
__device__ __align__(16) __half g_inter[B * N1 * DI];  // stage-1 result, fp16 point-major
__device__ int    g_idx1[B * N1 * 3];
__device__ float  g_w1[B * N1 * 3];
__device__ int    g_idx2[B * N0 * 3];
__device__ float  g_w2[B * N0 * 3];

// ---------------- transpose [B,R,C] fp32 -> fp32 ----------------
__global__ void transpose_kernel(const float* __restrict__ src, float* __restrict__ dst,
                                 int R, int C, int dstride, int dbstride) {
    __shared__ float tile[32][33];
    int b  = blockIdx.z;
    int c0 = blockIdx.x * 32, r0 = blockIdx.y * 32;
    const float* s = src + (size_t)b * R * C;
    float*       d = dst + (size_t)b * dbstride;
    int c = c0 + threadIdx.x;
    #pragma unroll
    for (int j = 0; j < 32; j += 8) {
        int r = r0 + threadIdx.y + j;
        tile[threadIdx.y + j][threadIdx.x] = s[(size_t)r * C + c];
    }
    __syncthreads();
    int rr = r0 + threadIdx.x;
    #pragma unroll
    for (int j = 0; j < 32; j += 8) {
        int cc = c0 + threadIdx.y + j;
        d[(size_t)cc * dstride + rr] = tile[threadIdx.x][threadIdx.y + j];
    }
}

// ---------------- transpose [B,R,C] fp32 -> fp16 dst ----------------
__global__ void transpose_half_kernel(const float* __restrict__ src, __half* __restrict__ dst,
                                      int R, int C, int dstride, int dbstride) {
    __shared__ float tile[32][33];
    int b  = blockIdx.z;
    int c0 = blockIdx.x * 32, r0 = blockIdx.y * 32;
    const float* s = src + (size_t)b * R * C;
    __half*      d = dst + (size_t)b * dbstride;
    int c = c0 + threadIdx.x;
    #pragma unroll
    for (int j = 0; j < 32; j += 8) {
        int r = r0 + threadIdx.y + j;
        tile[threadIdx.y + j][threadIdx.x] = s[(size_t)r * C + c];
    }
    __syncthreads();
    int rr = r0 + threadIdx.x;
    #pragma unroll
    for (int j = 0; j < 32; j += 8) {
        int cc = c0 + threadIdx.y + j;
        d[(size_t)cc * dstride + rr] = __float2half_rn(tile[threadIdx.x][threadIdx.y + j]);
    }
}

#define INS(E, SS)                                                                      \
    if ((E) < b2) {                                                                     \
        if ((E) < b0)      { b2 = b1; i2 = i1; b1 = b0; i1 = i0; b0 = (E); i0 = (SS); } \
        else if ((E) < b1) { b2 = b1; i2 = i1; b1 = (E); i1 = (SS); }                   \
        else               { b2 = (E); i2 = (SS); }                                     \
    }

// ---------------- warp-per-query top-3 (stage 1, S=512) ----------------
__global__ void topk_warp_kernel(const float* __restrict__ xyzq,
                                 const float* __restrict__ xyzs,
                                 int N, int S,
                                 int* __restrict__ idx, float* __restrict__ w) {
    extern __shared__ float4 sh[];
    const int qpb  = blockDim.x >> 5;
    int b    = blockIdx.x / (N / qpb);
    int n    = (blockIdx.x % (N / qpb)) * qpb + (threadIdx.x >> 5);
    int lane = threadIdx.x & 31;

    const float* sb = xyzs + (size_t)b * S * 3;
    for (int i = threadIdx.x; i < S; i += blockDim.x) {
        float x = sb[3 * i], y = sb[3 * i + 1], z = sb[3 * i + 2];
        sh[i] = make_float4(-2.f * x, -2.f * y, -2.f * z, x * x + y * y + z * z);
    }
    __syncthreads();

    const float* q = xyzq + ((size_t)b * N + n) * 3;
    float qx = q[0], qy = q[1], qz = q[2];

    float b0 = 1e30f, b1 = 1e30f, b2 = 1e30f;
    int   i0 = 0, i1 = 0, i2 = 0;

    #pragma unroll 4
    for (int s = lane; s < S; s += 32) {
        float4 p = sh[s];
        float e = fmaf(qx, p.x, fmaf(qy, p.y, fmaf(qz, p.z, p.w)));
        INS(e, s);
    }

    #pragma unroll
    for (int off = 16; off > 0; off >>= 1) {
        float c0 = __shfl_xor_sync(0xffffffffu, b0, off);
        float c1 = __shfl_xor_sync(0xffffffffu, b1, off);
        float c2 = __shfl_xor_sync(0xffffffffu, b2, off);
        int   j0 = __shfl_xor_sync(0xffffffffu, i0, off);
        int   j1 = __shfl_xor_sync(0xffffffffu, i1, off);
        int   j2 = __shfl_xor_sync(0xffffffffu, i2, off);
        INS(c0, j0);
        INS(c1, j1);
        INS(c2, j2);
    }

    if (lane == 0) {
        float cn = qx * qx + qy * qy + qz * qz;
        float r0 = 1.f / (cn + b0 + 1e-8f);
        float r1 = 1.f / (cn + b1 + 1e-8f);
        float r2 = 1.f / (cn + b2 + 1e-8f);
        float inv = 1.f / (r0 + r1 + r2);
        size_t o = ((size_t)b * N + n) * 3;
        idx[o] = i0; idx[o + 1] = i1; idx[o + 2] = i2;
        w[o]   = r0 * inv; w[o + 1] = r1 * inv; w[o + 2] = r2 * inv;
    }
}

// ---------------- quad-per-query top-3 (stage 2, S=2048) ----------------
__global__ __launch_bounds__(256) void topk_quad_kernel(const float* __restrict__ xyzq,
                                                        const float* __restrict__ xyzs,
                                                        int N, int S,
                                                        int* __restrict__ idx,
                                                        float* __restrict__ w) {
    extern __shared__ float4 sh[];
    int b      = blockIdx.x / (N / 64);
    int n_base = (blockIdx.x % (N / 64)) * 64;
    int t    = threadIdx.x;
    int warp = t >> 5;
    int lane = t & 31;
    int g    = lane >> 2;
    int l    = lane & 3;
    int n    = n_base + warp * 8 + g;

    const float* sb = xyzs + (size_t)b * S * 3;
    for (int i = t; i < S; i += 256) {
        float x = sb[3 * i], y = sb[3 * i + 1], z = sb[3 * i + 2];
        sh[i] = make_float4(-2.f * x, -2.f * y, -2.f * z, x * x + y * y + z * z);
    }
    __syncthreads();

    const float* q = xyzq + ((size_t)b * N + n) * 3;
    float qx = q[0], qy = q[1], qz = q[2];

    float b0 = 1e30f, b1 = 1e30f, b2 = 1e30f;
    int   i0 = 0, i1 = 0, i2 = 0;

    #pragma unroll 4
    for (int s = 2 * l; s < S; s += 8) {
        float4 p0 = sh[s];
        float4 p1 = sh[s + 1];
        float e0 = fmaf(qx, p0.x, fmaf(qy, p0.y, fmaf(qz, p0.z, p0.w)));
        float e1 = fmaf(qx, p1.x, fmaf(qy, p1.y, fmaf(qz, p1.z, p1.w)));
        if (fminf(e0, e1) < b2) {
            INS(e0, s);
            INS(e1, s + 1);
        }
    }

    #pragma unroll
    for (int off = 1; off <= 2; off <<= 1) {
        float c0 = __shfl_xor_sync(0xffffffffu, b0, off);
        float c1 = __shfl_xor_sync(0xffffffffu, b1, off);
        float c2 = __shfl_xor_sync(0xffffffffu, b2, off);
        int   j0 = __shfl_xor_sync(0xffffffffu, i0, off);
        int   j1 = __shfl_xor_sync(0xffffffffu, i1, off);
        int   j2 = __shfl_xor_sync(0xffffffffu, i2, off);
        INS(c0, j0);
        INS(c1, j1);
        INS(c2, j2);
    }

    if (l == 0) {
        float cn = qx * qx + qy * qy + qz * qz;
        float r0 = 1.f / (cn + b0 + 1e-8f);
        float r1 = 1.f / (cn + b1 + 1e-8f);
        float r2 = 1.f / (cn + b2 + 1e-8f);
        float inv = 1.f / (r0 + r1 + r2);
        size_t o = ((size_t)b * N + n) * 3;
        idx[o] = i0; idx[o + 1] = i1; idx[o + 2] = i2;
        w[o]   = r0 * inv; w[o + 1] = r1 * inv; w[o + 2] = r2 * inv;
    }
}
#undef INS

// ---------------- stage-1 gather: g_inter[:, 256:768] (fp16 store) ----------------
// grid (B*N1/32, D2C/64): 32-point x 64-channel tile per block, 256 threads.
__global__ __launch_bounds__(256) void gather1_kernel() {
    __shared__ int   sidx[32 * 3];
    __shared__ float sw[32 * 3];

    int b  = blockIdx.x / (N1 / 32);
    int n0 = (blockIdx.x % (N1 / 32)) * 32;
    int d0 = blockIdx.y * 64;
    int t  = threadIdx.x;

    if (t < 96) {
        size_t o = ((size_t)b * N1 + n0) * 3 + t;
        sidx[t] = g_idx1[o];
        sw[t]   = g_w1[o];
    }
    __syncthreads();

    const float* xb = g_x2t + (size_t)b * N2 * D2C + d0;
    __half* dstb = g_inter + ((size_t)b * N1 + n0) * DI + D1C + d0;

    // 32 points x 16 float4 chunks = 512 items, 2 per thread
    #pragma unroll
    for (int e = t; e < 32 * 16; e += 256) {
        int p = e >> 4;
        int v = (e & 15) * 4;
        int base = p * 3;
        float w0 = sw[base], w1 = sw[base + 1], w2 = sw[base + 2];
        float4 a = *(const float4*)(xb + (size_t)sidx[base]     * D2C + v);
        float4 c = *(const float4*)(xb + (size_t)sidx[base + 1] * D2C + v);
        float4 d = *(const float4*)(xb + (size_t)sidx[base + 2] * D2C + v);
        __half2 h0 = __floats2half2_rn(w0 * a.x + w1 * c.x + w2 * d.x,
                                       w0 * a.y + w1 * c.y + w2 * d.y);
        __half2 h1 = __floats2half2_rn(w0 * a.z + w1 * c.z + w2 * d.z,
                                       w0 * a.w + w1 * c.w + w2 * d.w);
        __half2* dp = (__half2*)(dstb + (size_t)p * DI + v);
        dp[0] = h0;
        dp[1] = h1;
    }
}

// ---------------- stage-2: out[:, 0:128] copy + out[:, 128:896] interp (fp16 gather) ----
// grid (B*N0/32, 13): y<12 -> interp chunk d0=y*64; y==12 -> x0 copy.
__global__ __launch_bounds__(256) void interp2_kernel(const float* __restrict__ x0,
                                                      float* __restrict__ out) {
    __shared__ float acc[32 * 65];
    __shared__ int   sidx[32 * 3];
    __shared__ float sw[32 * 3];

    int b  = blockIdx.x / (N0 / 32);
    int n0 = (blockIdx.x % (N0 / 32)) * 32;
    int t  = threadIdx.x;

    if (blockIdx.y == 12) {
        const float4* x04 = reinterpret_cast<const float4*>(x0) + (size_t)b * D0 * (N0 / 4);
        float4*       o4  = reinterpret_cast<float4*>(out)      + (size_t)b * DT * (N0 / 4);
        int q0 = n0 / 4;
        #pragma unroll
        for (int e = t; e < D0 * 8; e += 256) {
            int dd = e >> 3;
            int q  = e & 7;
            o4[(size_t)dd * (N0 / 4) + q0 + q] = x04[(size_t)dd * (N0 / 4) + q0 + q];
        }
        return;
    }

    int d0 = blockIdx.y * 64;

    if (t < 96) {
        size_t o = ((size_t)b * N0 + n0) * 3 + t;
        sidx[t] = g_idx2[o];
        sw[t]   = g_w2[o];
    }
    __syncthreads();

    const __half* interb = g_inter + (size_t)b * N1 * DI + d0;
    float* outb = out + (size_t)b * DT * N0 + (size_t)(D0 + d0) * N0 + n0;

    // gather-accumulate: 32 points x 8 chunks of 8 halves = 256 items (1/thread)
    {
        int p  = t >> 3;
        int c8 = (t & 7) * 8;
        int base = p * 3;
        float w0 = sw[base], w1 = sw[base + 1], w2 = sw[base + 2];
        const __half2* r0 = (const __half2*)(interb + (size_t)sidx[base]     * DI + c8);
        const __half2* r1 = (const __half2*)(interb + (size_t)sidx[base + 1] * DI + c8);
        const __half2* r2 = (const __half2*)(interb + (size_t)sidx[base + 2] * DI + c8);
        float* ap = acc + p * 65 + c8;
        #pragma unroll
        for (int j = 0; j < 4; ++j) {
            float2 a = __half22float2(r0[j]);
            float2 c = __half22float2(r1[j]);
            float2 d = __half22float2(r2[j]);
            ap[2 * j]     = w0 * a.x + w1 * c.x + w2 * d.x;
            ap[2 * j + 1] = w0 * a.y + w1 * c.y + w2 * d.y;
        }
    }
    __syncthreads();
    // write transposed: consecutive threads -> consecutive n (coalesced)
    #pragma unroll
    for (int e = t; e < 32 * 64; e += 256) {
        int dd = e >> 5;
        int p  = e & 31;
        outb[(size_t)dd * N0 + p] = acc[p * 65 + dd];
    }
}

// ---------------- stream/event singletons (host objects, created once, pre-capture) ----
static cudaStream_t side_stream() {
    static cudaStream_t s = [] {
        cudaStream_t t;
        cudaStreamCreateWithFlags(&t, cudaStreamNonBlocking);
        return t;
    }();
    return s;
}
static cudaEvent_t fork_event() {
    static cudaEvent_t e = [] {
        cudaEvent_t t;
        cudaEventCreateWithFlags(&t, cudaEventDisableTiming);
        return t;
    }();
    return e;
}
static cudaEvent_t join_event() {
    static cudaEvent_t e = [] {
        cudaEvent_t t;
        cudaEventCreateWithFlags(&t, cudaEventDisableTiming);
        return t;
    }();
    return e;
}

// ---------------- launch ----------------
extern "C" void kernel_launch(void* const* d_in, const int* in_sizes, int n_in,
                              void* d_out, int out_size) {
    const float* xyz0 = (const float*)d_in[0];  // [4,8192,3]
    const float* xyz1 = (const float*)d_in[1];  // [4,2048,3]
    const float* xyz2 = (const float*)d_in[2];  // [4,512,3]
    const float* x0   = (const float*)d_in[3];  // [4,128,8192]
    const float* x1   = (const float*)d_in[4];  // [4,256,2048]
    const float* x2   = (const float*)d_in[5];  // [4,512,512]
    float* out = (float*)d_out;

    float* x2t_ptr;   cudaGetSymbolAddress((void**)&x2t_ptr, g_x2t);
    __half* inter_ptr; cudaGetSymbolAddress((void**)&inter_ptr, g_inter);
    int* idx1_ptr;    cudaGetSymbolAddress((void**)&idx1_ptr, g_idx1);
    float* w1_ptr;    cudaGetSymbolAddress((void**)&w1_ptr, g_w1);
    int* idx2_ptr;    cudaGetSymbolAddress((void**)&idx2_ptr, g_idx2);
    float* w2_ptr;    cudaGetSymbolAddress((void**)&w2_ptr, g_w2);

    cudaStream_t s2 = side_stream();
    cudaEvent_t evF = fork_event(), evJ = join_event();

    // fork: stage-2 topk (depends only on xyz0, xyz1) runs on the side branch
    cudaEventRecord(evF, 0);
    cudaStreamWaitEvent(s2, evF, 0);
    topk_quad_kernel<<<B * N0 / 64, 256, N1 * sizeof(float4), s2>>>(
        xyz0, xyz1, N0, N1, idx2_ptr, w2_ptr);
    cudaEventRecord(evJ, s2);

    // main branch: stage-1 chain
    {
        dim3 grid(N2 / 32, D2C / 32, B), blk(32, 8);
        transpose_kernel<<<grid, blk>>>(x2, x2t_ptr, D2C, N2, D2C, N2 * D2C);
    }
    topk_warp_kernel<<<B * N1 / 32, 1024, N2 * sizeof(float4)>>>(
        xyz1, xyz2, N1, N2, idx1_ptr, w1_ptr);
    {
        dim3 grid(B * (N1 / 32), D2C / 64);
        gather1_kernel<<<grid, 256>>>();
    }
    {
        dim3 grid(N1 / 32, D1C / 32, B), blk(32, 8);
        transpose_half_kernel<<<grid, blk>>>(x1, inter_ptr, D1C, N1, DI, N1 * DI);
    }

    // join, then final interp
    cudaStreamWaitEvent(0, evJ, 0);
    {
        dim3 grid(B * (N0 / 32), 13);
        interp2_kernel<<<grid, 256>>>(x0, out);
    }
}

// round 14
// speedup vs baseline: 2.1602x; 1.0232x over previous
#include <cuda_runtime.h>
#include <cuda_fp16.h>
#include <math.h>

// ---------------- problem constants ----------------
#define B   4
#define N0  8192   // finest
#define N1  2048
#define N2  512    // coarsest
#define D0  128    // x0 channels
#define D1C 256    // x1 channels
#define D2C 512    // x2 channels
#define DI  768    // intermediate channels (D1C + D2C)
#define DT  896    // output channels (D0 + DI)

// ---------------- scratch (device globals; no allocation allowed) ----------------
__device__ __align__(16) __half g_x2t[B * N2 * D2C];   // x2 transposed, fp16 [B,S,D]
__device__ __align__(16) __half g_inter[B * N1 * DI];  // stage-1 result, fp16 point-major
__device__ int    g_idx1[B * N1 * 3];
__device__ float  g_w1[B * N1 * 3];
__device__ int    g_idx2[B * N0 * 3];
__device__ float  g_w2[B * N0 * 3];

// ---------------- transpose [B,R,C] fp32 -> fp16 dst (strided) ----------------
__global__ void transpose_half_kernel(const float* __restrict__ src, __half* __restrict__ dst,
                                      int R, int C, int dstride, int dbstride) {
    __shared__ float tile[32][33];
    int b  = blockIdx.z;
    int c0 = blockIdx.x * 32, r0 = blockIdx.y * 32;
    const float* s = src + (size_t)b * R * C;
    __half*      d = dst + (size_t)b * dbstride;
    int c = c0 + threadIdx.x;
    #pragma unroll
    for (int j = 0; j < 32; j += 8) {
        int r = r0 + threadIdx.y + j;
        tile[threadIdx.y + j][threadIdx.x] = s[(size_t)r * C + c];
    }
    __syncthreads();
    int rr = r0 + threadIdx.x;
    #pragma unroll
    for (int j = 0; j < 32; j += 8) {
        int cc = c0 + threadIdx.y + j;
        d[(size_t)cc * dstride + rr] = __float2half_rn(tile[threadIdx.x][threadIdx.y + j]);
    }
}

#define INS(E, SS)                                                                      \
    if ((E) < b2) {                                                                     \
        if ((E) < b0)      { b2 = b1; i2 = i1; b1 = b0; i1 = i0; b0 = (E); i0 = (SS); } \
        else if ((E) < b1) { b2 = b1; i2 = i1; b1 = (E); i1 = (SS); }                   \
        else               { b2 = (E); i2 = (SS); }                                     \
    }

// ---------------- warp-per-query top-3 (stage 1, S=512) ----------------
__global__ void topk_warp_kernel(const float* __restrict__ xyzq,
                                 const float* __restrict__ xyzs,
                                 int N, int S,
                                 int* __restrict__ idx, float* __restrict__ w) {
    extern __shared__ float4 sh[];
    const int qpb  = blockDim.x >> 5;
    int b    = blockIdx.x / (N / qpb);
    int n    = (blockIdx.x % (N / qpb)) * qpb + (threadIdx.x >> 5);
    int lane = threadIdx.x & 31;

    const float* sb = xyzs + (size_t)b * S * 3;
    for (int i = threadIdx.x; i < S; i += blockDim.x) {
        float x = sb[3 * i], y = sb[3 * i + 1], z = sb[3 * i + 2];
        sh[i] = make_float4(-2.f * x, -2.f * y, -2.f * z, x * x + y * y + z * z);
    }
    __syncthreads();

    const float* q = xyzq + ((size_t)b * N + n) * 3;
    float qx = q[0], qy = q[1], qz = q[2];

    float b0 = 1e30f, b1 = 1e30f, b2 = 1e30f;
    int   i0 = 0, i1 = 0, i2 = 0;

    #pragma unroll 4
    for (int s = lane; s < S; s += 32) {
        float4 p = sh[s];
        float e = fmaf(qx, p.x, fmaf(qy, p.y, fmaf(qz, p.z, p.w)));
        INS(e, s);
    }

    #pragma unroll
    for (int off = 16; off > 0; off >>= 1) {
        float c0 = __shfl_xor_sync(0xffffffffu, b0, off);
        float c1 = __shfl_xor_sync(0xffffffffu, b1, off);
        float c2 = __shfl_xor_sync(0xffffffffu, b2, off);
        int   j0 = __shfl_xor_sync(0xffffffffu, i0, off);
        int   j1 = __shfl_xor_sync(0xffffffffu, i1, off);
        int   j2 = __shfl_xor_sync(0xffffffffu, i2, off);
        INS(c0, j0);
        INS(c1, j1);
        INS(c2, j2);
    }

    if (lane == 0) {
        float cn = qx * qx + qy * qy + qz * qz;
        float r0 = 1.f / (cn + b0 + 1e-8f);
        float r1 = 1.f / (cn + b1 + 1e-8f);
        float r2 = 1.f / (cn + b2 + 1e-8f);
        float inv = 1.f / (r0 + r1 + r2);
        size_t o = ((size_t)b * N + n) * 3;
        idx[o] = i0; idx[o + 1] = i1; idx[o + 2] = i2;
        w[o]   = r0 * inv; w[o + 1] = r1 * inv; w[o + 2] = r2 * inv;
    }
}

// ---------------- quad-per-query top-3 (stage 2, S=2048) ----------------
__global__ __launch_bounds__(256) void topk_quad_kernel(const float* __restrict__ xyzq,
                                                        const float* __restrict__ xyzs,
                                                        int N, int S,
                                                        int* __restrict__ idx,
                                                        float* __restrict__ w) {
    extern __shared__ float4 sh[];
    int b      = blockIdx.x / (N / 64);
    int n_base = (blockIdx.x % (N / 64)) * 64;
    int t    = threadIdx.x;
    int warp = t >> 5;
    int lane = t & 31;
    int g    = lane >> 2;
    int l    = lane & 3;
    int n    = n_base + warp * 8 + g;

    const float* sb = xyzs + (size_t)b * S * 3;
    for (int i = t; i < S; i += 256) {
        float x = sb[3 * i], y = sb[3 * i + 1], z = sb[3 * i + 2];
        sh[i] = make_float4(-2.f * x, -2.f * y, -2.f * z, x * x + y * y + z * z);
    }
    __syncthreads();

    const float* q = xyzq + ((size_t)b * N + n) * 3;
    float qx = q[0], qy = q[1], qz = q[2];

    float b0 = 1e30f, b1 = 1e30f, b2 = 1e30f;
    int   i0 = 0, i1 = 0, i2 = 0;

    #pragma unroll 4
    for (int s = 2 * l; s < S; s += 8) {
        float4 p0 = sh[s];
        float4 p1 = sh[s + 1];
        float e0 = fmaf(qx, p0.x, fmaf(qy, p0.y, fmaf(qz, p0.z, p0.w)));
        float e1 = fmaf(qx, p1.x, fmaf(qy, p1.y, fmaf(qz, p1.z, p1.w)));
        if (fminf(e0, e1) < b2) {
            INS(e0, s);
            INS(e1, s + 1);
        }
    }

    #pragma unroll
    for (int off = 1; off <= 2; off <<= 1) {
        float c0 = __shfl_xor_sync(0xffffffffu, b0, off);
        float c1 = __shfl_xor_sync(0xffffffffu, b1, off);
        float c2 = __shfl_xor_sync(0xffffffffu, b2, off);
        int   j0 = __shfl_xor_sync(0xffffffffu, i0, off);
        int   j1 = __shfl_xor_sync(0xffffffffu, i1, off);
        int   j2 = __shfl_xor_sync(0xffffffffu, i2, off);
        INS(c0, j0);
        INS(c1, j1);
        INS(c2, j2);
    }

    if (l == 0) {
        float cn = qx * qx + qy * qy + qz * qz;
        float r0 = 1.f / (cn + b0 + 1e-8f);
        float r1 = 1.f / (cn + b1 + 1e-8f);
        float r2 = 1.f / (cn + b2 + 1e-8f);
        float inv = 1.f / (r0 + r1 + r2);
        size_t o = ((size_t)b * N + n) * 3;
        idx[o] = i0; idx[o + 1] = i1; idx[o + 2] = i2;
        w[o]   = r0 * inv; w[o + 1] = r1 * inv; w[o + 2] = r2 * inv;
    }
}
#undef INS

// ---------------- stage-1 gather: g_inter[:, 256:768] (fp16 in, fp16 out) ----------------
// grid (B*N1/32, D2C/64): 32-point x 64-channel tile per block, 256 threads.
__global__ __launch_bounds__(256) void gather1_kernel() {
    __shared__ int   sidx[32 * 3];
    __shared__ float sw[32 * 3];

    int b  = blockIdx.x / (N1 / 32);
    int n0 = (blockIdx.x % (N1 / 32)) * 32;
    int d0 = blockIdx.y * 64;
    int t  = threadIdx.x;

    if (t < 96) {
        size_t o = ((size_t)b * N1 + n0) * 3 + t;
        sidx[t] = g_idx1[o];
        sw[t]   = g_w1[o];
    }
    __syncthreads();

    const __half* xb = g_x2t + (size_t)b * N2 * D2C + d0;
    __half* dstb = g_inter + ((size_t)b * N1 + n0) * DI + D1C + d0;

    // 32 points x 8 chunks of 8 halves = 256 items, 1 per thread
    int p  = t >> 3;
    int c8 = (t & 7) * 8;
    int base = p * 3;
    float w0 = sw[base], w1 = sw[base + 1], w2 = sw[base + 2];
    const __half2* r0 = (const __half2*)(xb + (size_t)sidx[base]     * D2C + c8);
    const __half2* r1 = (const __half2*)(xb + (size_t)sidx[base + 1] * D2C + c8);
    const __half2* r2 = (const __half2*)(xb + (size_t)sidx[base + 2] * D2C + c8);
    __half2* dp = (__half2*)(dstb + (size_t)p * DI + c8);
    #pragma unroll
    for (int j = 0; j < 4; ++j) {
        float2 a = __half22float2(r0[j]);
        float2 c = __half22float2(r1[j]);
        float2 d = __half22float2(r2[j]);
        dp[j] = __floats2half2_rn(w0 * a.x + w1 * c.x + w2 * d.x,
                                  w0 * a.y + w1 * c.y + w2 * d.y);
    }
}

// ---------------- x0 copy: out[:, 0:128, :] (independent; overlapped branch) ----------
__global__ __launch_bounds__(256) void copy_x0_kernel(const float* __restrict__ x0,
                                                      float* __restrict__ out) {
    const int per_b = D0 * N0 / 4;          // float4s per batch
    int i = blockIdx.x * blockDim.x + threadIdx.x;
    if (i < B * per_b) {
        int b = i / per_b, r = i % per_b;
        reinterpret_cast<float4*>(out)[(size_t)b * (DT * N0 / 4) + r] =
            reinterpret_cast<const float4*>(x0)[i];
    }
}

// ---------------- stage-2 interp: out[:, 128:896] (fp16 gather) ----------------
// grid (B*N0/32, 12): one 32-point x 64-channel tile per block.
__global__ __launch_bounds__(256) void interp2_kernel(float* __restrict__ out) {
    __shared__ float acc[32 * 65];
    __shared__ int   sidx[32 * 3];
    __shared__ float sw[32 * 3];

    int b  = blockIdx.x / (N0 / 32);
    int n0 = (blockIdx.x % (N0 / 32)) * 32;
    int t  = threadIdx.x;
    int d0 = blockIdx.y * 64;

    if (t < 96) {
        size_t o = ((size_t)b * N0 + n0) * 3 + t;
        sidx[t] = g_idx2[o];
        sw[t]   = g_w2[o];
    }
    __syncthreads();

    const __half* interb = g_inter + (size_t)b * N1 * DI + d0;
    float* outb = out + (size_t)b * DT * N0 + (size_t)(D0 + d0) * N0 + n0;

    // gather-accumulate: 32 points x 8 chunks of 8 halves = 256 items (1/thread)
    {
        int p  = t >> 3;
        int c8 = (t & 7) * 8;
        int base = p * 3;
        float w0 = sw[base], w1 = sw[base + 1], w2 = sw[base + 2];
        const __half2* r0 = (const __half2*)(interb + (size_t)sidx[base]     * DI + c8);
        const __half2* r1 = (const __half2*)(interb + (size_t)sidx[base + 1] * DI + c8);
        const __half2* r2 = (const __half2*)(interb + (size_t)sidx[base + 2] * DI + c8);
        float* ap = acc + p * 65 + c8;
        #pragma unroll
        for (int j = 0; j < 4; ++j) {
            float2 a = __half22float2(r0[j]);
            float2 c = __half22float2(r1[j]);
            float2 d = __half22float2(r2[j]);
            ap[2 * j]     = w0 * a.x + w1 * c.x + w2 * d.x;
            ap[2 * j + 1] = w0 * a.y + w1 * c.y + w2 * d.y;
        }
    }
    __syncthreads();
    // write transposed: consecutive threads -> consecutive n (coalesced)
    #pragma unroll
    for (int e = t; e < 32 * 64; e += 256) {
        int dd = e >> 5;
        int p  = e & 31;
        outb[(size_t)dd * N0 + p] = acc[p * 65 + dd];
    }
}

// ---------------- stream/event singletons (host objects, created once, pre-capture) ----
struct GraphResources {
    cudaStream_t s2;
    cudaEvent_t  evF, evJ, evC;
    GraphResources() {
        cudaStreamCreateWithFlags(&s2, cudaStreamNonBlocking);
        cudaEventCreateWithFlags(&evF, cudaEventDisableTiming);
        cudaEventCreateWithFlags(&evJ, cudaEventDisableTiming);
        cudaEventCreateWithFlags(&evC, cudaEventDisableTiming);
    }
};
static GraphResources& gr() {
    static GraphResources r;
    return r;
}

// ---------------- launch ----------------
extern "C" void kernel_launch(void* const* d_in, const int* in_sizes, int n_in,
                              void* d_out, int out_size) {
    const float* xyz0 = (const float*)d_in[0];  // [4,8192,3]
    const float* xyz1 = (const float*)d_in[1];  // [4,2048,3]
    const float* xyz2 = (const float*)d_in[2];  // [4,512,3]
    const float* x0   = (const float*)d_in[3];  // [4,128,8192]
    const float* x1   = (const float*)d_in[4];  // [4,256,2048]
    const float* x2   = (const float*)d_in[5];  // [4,512,512]
    float* out = (float*)d_out;

    __half* x2t_ptr;   cudaGetSymbolAddress((void**)&x2t_ptr, g_x2t);
    __half* inter_ptr; cudaGetSymbolAddress((void**)&inter_ptr, g_inter);
    int* idx1_ptr;    cudaGetSymbolAddress((void**)&idx1_ptr, g_idx1);
    float* w1_ptr;    cudaGetSymbolAddress((void**)&w1_ptr, g_w1);
    int* idx2_ptr;    cudaGetSymbolAddress((void**)&idx2_ptr, g_idx2);
    float* w2_ptr;    cudaGetSymbolAddress((void**)&w2_ptr, g_w2);

    GraphResources& R = gr();

    // fork: side branch = stage-2 topk (xyz only) then the independent x0 copy
    cudaEventRecord(R.evF, 0);
    cudaStreamWaitEvent(R.s2, R.evF, 0);
    topk_quad_kernel<<<B * N0 / 64, 256, N1 * sizeof(float4), R.s2>>>(
        xyz0, xyz1, N0, N1, idx2_ptr, w2_ptr);
    cudaEventRecord(R.evJ, R.s2);                          // idx2/w2 ready
    copy_x0_kernel<<<(B * D0 * N0 / 4 + 255) / 256, 256, 0, R.s2>>>(x0, out);
    cudaEventRecord(R.evC, R.s2);                          // copy done (joined at end)

    // main branch: stage-1 chain
    {
        dim3 grid(N2 / 32, D2C / 32, B), blk(32, 8);
        transpose_half_kernel<<<grid, blk>>>(x2, x2t_ptr, D2C, N2, D2C, N2 * D2C);
    }
    topk_warp_kernel<<<B * N1 / 32, 1024, N2 * sizeof(float4)>>>(
        xyz1, xyz2, N1, N2, idx1_ptr, w1_ptr);
    {
        dim3 grid(B * (N1 / 32), D2C / 64);
        gather1_kernel<<<grid, 256>>>();
    }
    {
        dim3 grid(N1 / 32, D1C / 32, B), blk(32, 8);
        transpose_half_kernel<<<grid, blk>>>(x1, inter_ptr, D1C, N1, DI, N1 * DI);
    }

    // join idx2, run final interp (overlaps with the x0 copy on s2)
    cudaStreamWaitEvent(0, R.evJ, 0);
    {
        dim3 grid(B * (N0 / 32), 12);
        interp2_kernel<<<grid, 256>>>(out);
    }
    // join the copy branch before capture ends
    cudaStreamWaitEvent(0, R.evC, 0);
}